// round 7
// baseline (speedup 1.0000x reference)
#include <cuda_runtime.h>
#include <cuda_bf16.h>
#include <cstdint>

// RecursiveEncoder — mma.sync bf16 3-term split, ldmatrix fragments,
// 512 threads (16 warps), double-buffered 16-k weight chunks.
//
// Warp (wm,wn): wm=wid>>2 rows wm*16..+15; wn=wid&3 cols wn*64..+63.
// Per k16 chunk per warp: 2 A LDSM.x4 (hi/lo) + 8 B LDSM.x4 + 24 MMAs.

#define NT    512
#define PT    64
#define GRID  512
#define MAXC  10

#define ASTR  264          // A row stride (bf16): 528B -> 4i banks, LDSM conflict-free
#define MSTR  260          // macc row stride (f32)
#define WKS   24           // W chunk row stride (bf16): 48B -> 12i banks, conflict-free
#define WBUF  12288        // one W chunk buffer: 256 * 48B

// ---- smem offsets (bytes) ----
#define OFF_AHI   0          // 64*264*2 = 33792
#define OFF_ALO   33792
#define OFF_MACC  67584      // 64*260*4 = 66560
#define OFF_WH    134144     // 2 bufs * 12288
#define OFF_WL    158720     // 2 bufs * 12288
#define OFF_BOX   183296     // 64*10*4
#define OFF_B1    185856
#define OFF_B2    186880
#define OFF_BS1   187904
#define OFF_BMU   188928
#define OFF_BVAR  189952
#define OFF_SEM   190976     // 64*10*4
#define OFF_NC    193536     // 64*4
#define SMEM_SZ   193792

__device__ __nv_bfloat16 g_WT_hi[5 * 65536];   // [layer][n][k]
__device__ __nv_bfloat16 g_WT_lo[5 * 65536];

static __device__ __forceinline__ uint32_t smem_u32(const void* p) {
    uint32_t a;
    asm("{ .reg .u64 t; cvta.to.shared.u64 t, %1; cvt.u32.u64 %0, t; }"
        : "=r"(a) : "l"(p));
    return a;
}
static __device__ __forceinline__ void mma16816(float d[4], const uint32_t a[4],
                                                uint32_t b0, uint32_t b1)
{
    asm volatile(
        "mma.sync.aligned.m16n8k16.row.col.f32.bf16.bf16.f32 "
        "{%0,%1,%2,%3}, {%4,%5,%6,%7}, {%8,%9}, {%0,%1,%2,%3};"
        : "+f"(d[0]), "+f"(d[1]), "+f"(d[2]), "+f"(d[3])
        : "r"(a[0]), "r"(a[1]), "r"(a[2]), "r"(a[3]), "r"(b0), "r"(b1));
}
static __device__ __forceinline__ void ldsm_x4(uint32_t r[4], uint32_t addr) {
    asm volatile("ldmatrix.sync.aligned.m8n8.x4.shared.b16 {%0,%1,%2,%3}, [%4];"
                 : "=r"(r[0]), "=r"(r[1]), "=r"(r[2]), "=r"(r[3]) : "r"(addr));
}

// ---- prep: transpose + bf16 hi/lo split of the 5 [256,256] weight mats ----
__global__ void prep_weights(const float* __restrict__ W1, const float* __restrict__ W2,
                             const float* __restrict__ Ws1, const float* __restrict__ Wmu,
                             const float* __restrict__ Wvar)
{
    int idx = blockIdx.x * blockDim.x + threadIdx.x;
    int l = idx >> 16;
    int e = idx & 65535;
    int n = e >> 8, k = e & 255;
    const float* src = (l == 0) ? W1 : (l == 1) ? W2 : (l == 2) ? Ws1 : (l == 3) ? Wmu : Wvar;
    float v = src[k * 256 + n];
    __nv_bfloat16 h = __float2bfloat16(v);
    g_WT_hi[idx] = h;
    g_WT_lo[idx] = __float2bfloat16(v - __bfloat162float(h));
}

// ---- full K=256 GEMM: C[16 rows x 64 cols per warp], 3-term bf16 split ----
static __device__ __forceinline__ void gemm_tc(char* sm, uint32_t smb,
                                               const __nv_bfloat16* __restrict__ whi,
                                               const __nv_bfloat16* __restrict__ wlo,
                                               int t, int lane, int wm, int wn,
                                               float C[8][4])
{
    #pragma unroll
    for (int nt = 0; nt < 8; nt++)
        #pragma unroll
        for (int q = 0; q < 4; q++) C[nt][q] = 0.0f;

    // LDSM lane addresses
    const int arow = (lane & 7) + ((lane >> 3) & 1) * 8;
    const int akoff = (lane >> 4) * 8;
    uint32_t aHi = smb + OFF_AHI + (uint32_t)(((wm * 16 + arow) * ASTR + akoff) * 2);
    uint32_t aLo = aHi + (OFF_ALO - OFF_AHI);
    const int brow = (lane & 7) + ((lane >> 4) & 1) * 8;
    const int bkoff = ((lane >> 3) & 1) * 8;
    const uint32_t bRel = (uint32_t)(((wn * 64 + brow) * WKS + bkoff) * 2);
    const uint32_t wh0 = smb + OFF_WH, wl0 = smb + OFF_WL;

    // W chunk LDG/STS mapping: thread t owns n = t>>1, khalf = (t&1)*8
    const uint4* gh = (const uint4*)(whi + (t >> 1) * 256 + (t & 1) * 8);
    const uint4* gl = (const uint4*)(wlo + (t >> 1) * 256 + (t & 1) * 8);
    const uint32_t stoff = (uint32_t)((t >> 1) * 48 + (t & 1) * 16);

    uint4 ph = gh[0], pl = gl[0];
    *(uint4*)(sm + OFF_WH + stoff) = ph;
    *(uint4*)(sm + OFF_WL + stoff) = pl;
    __syncthreads();

    #pragma unroll 1
    for (int c = 0; c < 16; c++) {
        if (c < 15) { ph = gh[(c + 1) * 2]; pl = gl[(c + 1) * 2]; }

        const uint32_t bsel = (uint32_t)(c & 1) * WBUF;
        uint32_t ah[4], al[4];
        ldsm_x4(ah, aHi + c * 32);
        ldsm_x4(al, aLo + c * 32);
        #pragma unroll
        for (int nt2 = 0; nt2 < 4; nt2++) {
            uint32_t bh[4], bl[4];
            ldsm_x4(bh, wh0 + bsel + bRel + nt2 * 768);
            ldsm_x4(bl, wl0 + bsel + bRel + nt2 * 768);
            mma16816(C[nt2 * 2],     ah, bh[0], bh[1]);
            mma16816(C[nt2 * 2],     al, bh[0], bh[1]);
            mma16816(C[nt2 * 2],     ah, bl[0], bl[1]);
            mma16816(C[nt2 * 2 + 1], ah, bh[2], bh[3]);
            mma16816(C[nt2 * 2 + 1], al, bh[2], bh[3]);
            mma16816(C[nt2 * 2 + 1], ah, bl[2], bl[3]);
        }

        if (c < 15) {
            const uint32_t nsel = (uint32_t)((c + 1) & 1) * WBUF;
            *(uint4*)(sm + OFF_WH + nsel + stoff) = ph;
            *(uint4*)(sm + OFF_WL + nsel + stoff) = pl;
        }
        __syncthreads();
    }
    // trailing barrier of last iteration also protects A for the caller
}

static __device__ __forceinline__ void split_pair(__nv_bfloat16* Ahi, __nv_bfloat16* Alo,
                                                  int idx, float s0, float s1)
{
    __nv_bfloat162 h2 = __float22bfloat162_rn(make_float2(s0, s1));
    float r0 = s0 - __bfloat162float(__low2bfloat16(h2));
    float r1 = s1 - __bfloat162float(__high2bfloat16(h2));
    __nv_bfloat162 l2 = __float22bfloat162_rn(make_float2(r0, r1));
    *(uint32_t*)&Ahi[idx] = *(uint32_t*)&h2;
    *(uint32_t*)&Alo[idx] = *(uint32_t*)&l2;
}

__global__ void __launch_bounds__(NT, 1)
recenc_tc_kernel(const float* __restrict__ box_input,
                 const float* __restrict__ eps,
                 const float* __restrict__ W_box,
                 const float* __restrict__ b_box,
                 const float* __restrict__ W1,
                 const float* __restrict__ b1,
                 const float* __restrict__ b2,
                 const float* __restrict__ bs1,
                 const float* __restrict__ bmu,
                 const float* __restrict__ bvar,
                 const int*   __restrict__ sem_ids,
                 const int*   __restrict__ n_children,
                 float*       __restrict__ out)
{
    extern __shared__ char sm[];
    const uint32_t smb = smem_u32(sm);
    __nv_bfloat16* Ahi = (__nv_bfloat16*)(sm + OFF_AHI);
    __nv_bfloat16* Alo = (__nv_bfloat16*)(sm + OFF_ALO);
    float* maccS = (float*)(sm + OFF_MACC);
    float* boxS  = (float*)(sm + OFF_BOX);
    float* b1S   = (float*)(sm + OFF_B1);
    float* b2S   = (float*)(sm + OFF_B2);
    float* bs1S  = (float*)(sm + OFF_BS1);
    float* bmuS  = (float*)(sm + OFF_BMU);
    float* bvarS = (float*)(sm + OFF_BVAR);
    int*   semS  = (int*)(sm + OFF_SEM);
    int*   ncS   = (int*)(sm + OFF_NC);

    const int t = threadIdx.x;
    const int wid = t >> 5;
    const int lane = t & 31;
    const int wm = wid >> 2;
    const int wn = wid & 3;
    const int b0 = blockIdx.x * PT;

    // ---- stage constants, zero macc ----
    if (t < 256) {
        b1S[t]   = b1[t];
        b2S[t]   = b2[t];
        bs1S[t]  = bs1[t];
        bmuS[t]  = bmu[t];
        bvarS[t] = bvar[t];
    }
    for (int i = t; i < PT * 10; i += NT) semS[i] = sem_ids[b0 * 10 + i];
    if (t < PT) ncS[t] = n_children[b0 + t];
    for (int i = t; i < PT * MSTR; i += NT) maccS[i] = 0.0f;

    // ---- leaf weights resident in registers: this thread's fixed column pair ----
    const int fp = t & 127;           // pair index: cols f = 2*fp, 2*fp+1
    const int f0 = fp * 2;
    float2 wb[10], bbp;
    #pragma unroll
    for (int q = 0; q < 10; q++) wb[q] = *(const float2*)&W_box[q * 256 + f0];
    bbp = *(const float2*)&b_box[f0];

    float C[8][4];

    // ---- children: leaf -> GEMM(W1) -> masked max into maccS ----
    for (int m = 0; m < MAXC; m++) {
        for (int i = t; i < PT * 10; i += NT)
            boxS[i] = box_input[(b0 + i / 10) * 100 + m * 10 + (i % 10)];
        __syncthreads();

        // leaf = relu(box @ Wbox + bbox): 16 pairs per thread, fixed column pair
        #pragma unroll
        for (int u = 0; u < 16; u++) {
            int r = (t >> 7) + u * 4;
            float s0 = bbp.x, s1 = bbp.y;
            const float* bx = &boxS[r * 10];
            #pragma unroll
            for (int q = 0; q < 10; q++) {
                float b = bx[q];
                s0 += b * wb[q].x;
                s1 += b * wb[q].y;
            }
            split_pair(Ahi, Alo, r * ASTR + f0, fmaxf(s0, 0.0f), fmaxf(s1, 0.0f));
        }

        gemm_tc(sm, smb, g_WT_hi, g_WT_lo, t, lane, wm, wn, C);

        // epilogue: feat = relu(C + W1[256+sem] + b1); macc = max(macc, feat)
        #pragma unroll
        for (int half = 0; half < 2; half++) {
            int r = wm * 16 + (lane >> 2) + half * 8;
            if (m < ncS[r]) {
                const float* wrow = W1 + ((256 + semS[r * 10 + m]) << 8);
                #pragma unroll
                for (int nt = 0; nt < 8; nt++) {
                    int col = wn * 64 + nt * 8 + (lane & 3) * 2;
                    float2 w  = *(const float2*)&wrow[col];
                    float2 bb = *(const float2*)&b1S[col];
                    float v0 = fmaxf(C[nt][half * 2 + 0] + w.x + bb.x, 0.0f);
                    float v1 = fmaxf(C[nt][half * 2 + 1] + w.y + bb.y, 0.0f);
                    float2* mp = (float2*)&maccS[r * MSTR + col];
                    float2 mo = *mp;
                    mo.x = fmaxf(mo.x, v0);
                    mo.y = fmaxf(mo.y, v1);
                    *mp = mo;
                }
            }
        }
        __syncthreads();   // macc writes done before anyone proceeds
    }

    // split macc -> A (16 pairs per thread, fixed column pair)
    #define SPLIT_MACC_TO_A()                                                  \
        do {                                                                   \
            _Pragma("unroll")                                                  \
            for (int u = 0; u < 16; u++) {                                     \
                int r = (t >> 7) + u * 4;                                      \
                float2 v = *(const float2*)&maccS[r * MSTR + f0];              \
                split_pair(Ahi, Alo, r * ASTR + f0, v.x, v.y);                 \
            }                                                                  \
        } while (0)

    // ---- parent_feat = relu(X @ W2 + b2) ----
    SPLIT_MACC_TO_A();
    gemm_tc(sm, smb, g_WT_hi + 1 * 65536, g_WT_lo + 1 * 65536, t, lane, wm, wn, C);
    #pragma unroll
    for (int half = 0; half < 2; half++) {
        int r = wm * 16 + (lane >> 2) + half * 8;
        #pragma unroll
        for (int nt = 0; nt < 8; nt++) {
            int col = wn * 64 + nt * 8 + (lane & 3) * 2;
            float2 bb = *(const float2*)&b2S[col];
            float2 v;
            v.x = fmaxf(C[nt][half * 2 + 0] + bb.x, 0.0f);
            v.y = fmaxf(C[nt][half * 2 + 1] + bb.y, 0.0f);
            *(float2*)&maccS[r * MSTR + col] = v;
        }
    }
    __syncthreads();

    // ---- enc = relu(P @ Ws1 + bs1) ----
    SPLIT_MACC_TO_A();
    gemm_tc(sm, smb, g_WT_hi + 2 * 65536, g_WT_lo + 2 * 65536, t, lane, wm, wn, C);
    #pragma unroll
    for (int half = 0; half < 2; half++) {
        int r = wm * 16 + (lane >> 2) + half * 8;
        #pragma unroll
        for (int nt = 0; nt < 8; nt++) {
            int col = wn * 64 + nt * 8 + (lane & 3) * 2;
            float2 bb = *(const float2*)&bs1S[col];
            float2 v;
            v.x = fmaxf(C[nt][half * 2 + 0] + bb.x, 0.0f);
            v.y = fmaxf(C[nt][half * 2 + 1] + bb.y, 0.0f);
            *(float2*)&maccS[r * MSTR + col] = v;
        }
    }
    __syncthreads();

    // ---- mu = enc @ Wmu + bmu (enc stays in A; macc holds mu) ----
    SPLIT_MACC_TO_A();
    gemm_tc(sm, smb, g_WT_hi + 3 * 65536, g_WT_lo + 3 * 65536, t, lane, wm, wn, C);
    #pragma unroll
    for (int half = 0; half < 2; half++) {
        int r = wm * 16 + (lane >> 2) + half * 8;
        #pragma unroll
        for (int nt = 0; nt < 8; nt++) {
            int col = wn * 64 + nt * 8 + (lane & 3) * 2;
            float2 bb = *(const float2*)&bmuS[col];
            float2 v;
            v.x = C[nt][half * 2 + 0] + bb.x;
            v.y = C[nt][half * 2 + 1] + bb.y;
            *(float2*)&maccS[r * MSTR + col] = v;   // lane-owned, reread below
        }
    }

    // ---- logvar = enc @ Wvar + bvar; sampler epilogue ----
    gemm_tc(sm, smb, g_WT_hi + 4 * 65536, g_WT_lo + 4 * 65536, t, lane, wm, wn, C);
    float* kldF = (float*)(sm + OFF_AHI);   // reuse A region: [64][264] f32
    #pragma unroll
    for (int half = 0; half < 2; half++) {
        int r = wm * 16 + (lane >> 2) + half * 8;
        int b = b0 + r;
        #pragma unroll
        for (int nt = 0; nt < 8; nt++) {
            int col = wn * 64 + nt * 8 + (lane & 3) * 2;
            float2 bb = *(const float2*)&bvarS[col];
            float2 mv = *(const float2*)&maccS[r * MSTR + col];
            float2 e  = *(const float2*)&eps[b * 256 + col];
            float lvx = C[nt][half * 2 + 0] + bb.x;
            float lvy = C[nt][half * 2 + 1] + bb.y;
            float sdx = expf(0.5f * lvx);
            float sdy = expf(0.5f * lvy);
            float2 samp, kld;
            samp.x = e.x * sdx + mv.x;
            samp.y = e.y * sdy + mv.y;
            kld.x = 1.0f + lvx - mv.x * mv.x - sdx * sdx;
            kld.y = 1.0f + lvy - mv.y * mv.y - sdy * sdy;
            *(float2*)&maccS[r * MSTR + col] = samp;
            *(float2*)&kldF[r * 264 + col] = kld;
        }
    }
    __syncthreads();

    // ---- coalesced output sweep ----
    #pragma unroll 1
    for (int u = 0; u < (PT * 256) / NT; u++) {
        int i = t + u * NT;
        int r = i >> 8, f = i & 255;
        out[(b0 + r) * 512 + f]       = maccS[r * MSTR + f];
        out[(b0 + r) * 512 + 256 + f] = kldF[r * 264 + f];
    }
}

// ================= launch =================
extern "C" void kernel_launch(void* const* d_in, const int* in_sizes, int n_in,
                              void* d_out, int out_size)
{
    const float* box   = (const float*)d_in[0];
    const float* eps   = (const float*)d_in[1];
    const float* W_box = (const float*)d_in[2];
    const float* b_box = (const float*)d_in[3];
    const float* W1    = (const float*)d_in[4];
    const float* b1    = (const float*)d_in[5];
    const float* W2    = (const float*)d_in[6];
    const float* b2    = (const float*)d_in[7];
    const float* Ws1   = (const float*)d_in[8];
    const float* bs1   = (const float*)d_in[9];
    const float* Wmu   = (const float*)d_in[10];
    const float* bmu   = (const float*)d_in[11];
    const float* Wvar  = (const float*)d_in[12];
    const float* bvar  = (const float*)d_in[13];
    const int*   sem   = (const int*)d_in[14];
    const int*   nc    = (const int*)d_in[15];
    float* out = (float*)d_out;

    prep_weights<<<(5 * 65536) / 256, 256>>>(W1, W2, Ws1, Wmu, Wvar);

    cudaFuncSetAttribute(recenc_tc_kernel,
                         cudaFuncAttributeMaxDynamicSharedMemorySize, SMEM_SZ);
    recenc_tc_kernel<<<GRID, NT, SMEM_SZ>>>(
        box, eps, W_box, b_box, W1, b1, b2, bs1, bmu, bvar, sem, nc, out);
}

// round 8
// speedup vs baseline: 1.3478x; 1.3478x over previous
#include <cuda_runtime.h>
#include <cuda_bf16.h>
#include <cstdint>

// RecursiveEncoder — mma.sync bf16 3-term split, ldmatrix fragments,
// 512 threads (16 warps), double-buffered 16-k weight chunks.
// R8: B fragments preloaded per k16 step; MMAs term-major (dep distance 8).

#define NT    512
#define PT    64
#define GRID  512
#define MAXC  10

#define ASTR  264          // A row stride (bf16): 528B -> conflict-free LDSM
#define MSTR  260          // macc row stride (f32)
#define WKS   24           // W chunk row stride (bf16): 48B rows
#define WBUF  12288        // one W chunk buffer: 256 * 48B

// ---- smem offsets (bytes) ----
#define OFF_AHI   0          // 64*264*2 = 33792
#define OFF_ALO   33792
#define OFF_MACC  67584      // 64*260*4 = 66560
#define OFF_WH    134144     // 2 bufs * 12288
#define OFF_WL    158720     // 2 bufs * 12288
#define OFF_BOX   183296     // 64*10*4 = 2560
#define OFF_WBOX  185856     // 10*256*4 = 10240
#define OFF_BBOX  196096     // 1024
#define OFF_B1    197120
#define OFF_B2    198144
#define OFF_BS1   199168
#define OFF_BMU   200192
#define OFF_BVAR  201216
#define OFF_SEM   202240     // 2560
#define OFF_NC    204800     // 256
#define SMEM_SZ   205056

__device__ __nv_bfloat16 g_WT_hi[5 * 65536];   // [layer][n][k]
__device__ __nv_bfloat16 g_WT_lo[5 * 65536];

static __device__ __forceinline__ uint32_t smem_u32(const void* p) {
    uint32_t a;
    asm("{ .reg .u64 t; cvta.to.shared.u64 t, %1; cvt.u32.u64 %0, t; }"
        : "=r"(a) : "l"(p));
    return a;
}
static __device__ __forceinline__ void mma16816(float d[4], const uint32_t a[4],
                                                uint32_t b0, uint32_t b1)
{
    asm volatile(
        "mma.sync.aligned.m16n8k16.row.col.f32.bf16.bf16.f32 "
        "{%0,%1,%2,%3}, {%4,%5,%6,%7}, {%8,%9}, {%0,%1,%2,%3};"
        : "+f"(d[0]), "+f"(d[1]), "+f"(d[2]), "+f"(d[3])
        : "r"(a[0]), "r"(a[1]), "r"(a[2]), "r"(a[3]), "r"(b0), "r"(b1));
}
static __device__ __forceinline__ void ldsm_x4(uint32_t r[4], uint32_t addr) {
    asm volatile("ldmatrix.sync.aligned.m8n8.x4.shared.b16 {%0,%1,%2,%3}, [%4];"
                 : "=r"(r[0]), "=r"(r[1]), "=r"(r[2]), "=r"(r[3]) : "r"(addr));
}

// ---- prep: transpose + bf16 hi/lo split of the 5 [256,256] weight mats ----
__global__ void prep_weights(const float* __restrict__ W1, const float* __restrict__ W2,
                             const float* __restrict__ Ws1, const float* __restrict__ Wmu,
                             const float* __restrict__ Wvar)
{
    int idx = blockIdx.x * blockDim.x + threadIdx.x;
    int l = idx >> 16;
    int e = idx & 65535;
    int n = e >> 8, k = e & 255;
    const float* src = (l == 0) ? W1 : (l == 1) ? W2 : (l == 2) ? Ws1 : (l == 3) ? Wmu : Wvar;
    float v = src[k * 256 + n];
    __nv_bfloat16 h = __float2bfloat16(v);
    g_WT_hi[idx] = h;
    g_WT_lo[idx] = __float2bfloat16(v - __bfloat162float(h));
}

// ---- full K=256 GEMM: C[16 rows x 64 cols per warp], 3-term bf16 split ----
static __device__ __forceinline__ void gemm_tc(char* sm, uint32_t smb,
                                               const __nv_bfloat16* __restrict__ whi,
                                               const __nv_bfloat16* __restrict__ wlo,
                                               int t, int lane, int wm, int wn,
                                               float C[8][4])
{
    #pragma unroll
    for (int nt = 0; nt < 8; nt++)
        #pragma unroll
        for (int q = 0; q < 4; q++) C[nt][q] = 0.0f;

    // LDSM lane addresses
    const int arow = (lane & 7) + ((lane >> 3) & 1) * 8;
    const int akoff = (lane >> 4) * 8;
    uint32_t aHi = smb + OFF_AHI + (uint32_t)(((wm * 16 + arow) * ASTR + akoff) * 2);
    uint32_t aLo = aHi + (OFF_ALO - OFF_AHI);
    const int brow = (lane & 7) + ((lane >> 4) & 1) * 8;
    const int bkoff = ((lane >> 3) & 1) * 8;
    const uint32_t bRel = (uint32_t)(((wn * 64 + brow) * WKS + bkoff) * 2);
    const uint32_t wh0 = smb + OFF_WH, wl0 = smb + OFF_WL;

    // W chunk LDG/STS mapping: thread t owns n = t>>1, khalf = (t&1)*8
    const uint4* gh = (const uint4*)(whi + (t >> 1) * 256 + (t & 1) * 8);
    const uint4* gl = (const uint4*)(wlo + (t >> 1) * 256 + (t & 1) * 8);
    const uint32_t stoff = (uint32_t)((t >> 1) * 48 + (t & 1) * 16);

    uint4 ph = gh[0], pl = gl[0];
    *(uint4*)(sm + OFF_WH + stoff) = ph;
    *(uint4*)(sm + OFF_WL + stoff) = pl;
    __syncthreads();

    #pragma unroll 1
    for (int c = 0; c < 16; c++) {
        if (c < 15) { ph = gh[(c + 1) * 2]; pl = gl[(c + 1) * 2]; }

        const uint32_t bsel = (uint32_t)(c & 1) * WBUF;

        // --- load ALL fragments for this k16 step first ---
        uint32_t ah[4], al[4];
        ldsm_x4(ah, aHi + c * 32);
        ldsm_x4(al, aLo + c * 32);
        uint32_t bh[4][4], bl[4][4];
        #pragma unroll
        for (int nt2 = 0; nt2 < 4; nt2++) {
            ldsm_x4(bh[nt2], wh0 + bsel + bRel + nt2 * 768);
            ldsm_x4(bl[nt2], wl0 + bsel + bRel + nt2 * 768);
        }

        // --- 24 MMAs, term-major: dep distance 8 on every accumulator ---
        #pragma unroll
        for (int nt2 = 0; nt2 < 4; nt2++) {
            mma16816(C[nt2 * 2],     ah, bh[nt2][0], bh[nt2][1]);
            mma16816(C[nt2 * 2 + 1], ah, bh[nt2][2], bh[nt2][3]);
        }
        #pragma unroll
        for (int nt2 = 0; nt2 < 4; nt2++) {
            mma16816(C[nt2 * 2],     al, bh[nt2][0], bh[nt2][1]);
            mma16816(C[nt2 * 2 + 1], al, bh[nt2][2], bh[nt2][3]);
        }
        #pragma unroll
        for (int nt2 = 0; nt2 < 4; nt2++) {
            mma16816(C[nt2 * 2],     ah, bl[nt2][0], bl[nt2][1]);
            mma16816(C[nt2 * 2 + 1], ah, bl[nt2][2], bl[nt2][3]);
        }

        if (c < 15) {
            const uint32_t nsel = (uint32_t)((c + 1) & 1) * WBUF;
            *(uint4*)(sm + OFF_WH + nsel + stoff) = ph;
            *(uint4*)(sm + OFF_WL + nsel + stoff) = pl;
        }
        __syncthreads();
    }
    // trailing barrier of last iteration also protects A for the caller
}

static __device__ __forceinline__ void split_pair(__nv_bfloat16* Ahi, __nv_bfloat16* Alo,
                                                  int idx, float s0, float s1)
{
    __nv_bfloat162 h2 = __float22bfloat162_rn(make_float2(s0, s1));
    float r0 = s0 - __bfloat162float(__low2bfloat16(h2));
    float r1 = s1 - __bfloat162float(__high2bfloat16(h2));
    __nv_bfloat162 l2 = __float22bfloat162_rn(make_float2(r0, r1));
    *(uint32_t*)&Ahi[idx] = *(uint32_t*)&h2;
    *(uint32_t*)&Alo[idx] = *(uint32_t*)&l2;
}

__global__ void __launch_bounds__(NT, 1)
recenc_tc_kernel(const float* __restrict__ box_input,
                 const float* __restrict__ eps,
                 const float* __restrict__ W_box,
                 const float* __restrict__ b_box,
                 const float* __restrict__ W1,
                 const float* __restrict__ b1,
                 const float* __restrict__ b2,
                 const float* __restrict__ bs1,
                 const float* __restrict__ bmu,
                 const float* __restrict__ bvar,
                 const int*   __restrict__ sem_ids,
                 const int*   __restrict__ n_children,
                 float*       __restrict__ out)
{
    extern __shared__ char sm[];
    const uint32_t smb = smem_u32(sm);
    __nv_bfloat16* Ahi = (__nv_bfloat16*)(sm + OFF_AHI);
    __nv_bfloat16* Alo = (__nv_bfloat16*)(sm + OFF_ALO);
    float* maccS = (float*)(sm + OFF_MACC);
    float* boxS  = (float*)(sm + OFF_BOX);
    float* wboxS = (float*)(sm + OFF_WBOX);
    float* bboxS = (float*)(sm + OFF_BBOX);
    float* b1S   = (float*)(sm + OFF_B1);
    float* b2S   = (float*)(sm + OFF_B2);
    float* bs1S  = (float*)(sm + OFF_BS1);
    float* bmuS  = (float*)(sm + OFF_BMU);
    float* bvarS = (float*)(sm + OFF_BVAR);
    int*   semS  = (int*)(sm + OFF_SEM);
    int*   ncS   = (int*)(sm + OFF_NC);

    const int t = threadIdx.x;
    const int wid = t >> 5;
    const int lane = t & 31;
    const int wm = wid >> 2;
    const int wn = wid & 3;
    const int b0 = blockIdx.x * PT;

    // ---- stage constants, zero macc ----
    for (int i = t; i < 10 * 256; i += NT) wboxS[i] = W_box[i];
    if (t < 256) {
        bboxS[t] = b_box[t];
        b1S[t]   = b1[t];
        b2S[t]   = b2[t];
        bs1S[t]  = bs1[t];
        bmuS[t]  = bmu[t];
        bvarS[t] = bvar[t];
    }
    for (int i = t; i < PT * 10; i += NT) semS[i] = sem_ids[b0 * 10 + i];
    if (t < PT) ncS[t] = n_children[b0 + t];
    for (int i = t; i < PT * MSTR; i += NT) maccS[i] = 0.0f;

    const int fp = t & 127;           // pair index: cols f = 2*fp, 2*fp+1
    const int f0 = fp * 2;

    float C[8][4];

    // ---- children: leaf -> GEMM(W1) -> masked max into maccS ----
    for (int m = 0; m < MAXC; m++) {
        for (int i = t; i < PT * 10; i += NT)
            boxS[i] = box_input[(b0 + i / 10) * 100 + m * 10 + (i % 10)];
        __syncthreads();

        // leaf = relu(box @ Wbox + bbox): 16 pairs per thread, fixed column pair
        float2 bbp = *(const float2*)&bboxS[f0];
        #pragma unroll 4
        for (int u = 0; u < 16; u++) {
            int r = (t >> 7) + u * 4;
            float s0 = bbp.x, s1 = bbp.y;
            const float* bx = &boxS[r * 10];
            #pragma unroll
            for (int q = 0; q < 10; q++) {
                float b = bx[q];
                float2 w = *(const float2*)&wboxS[q * 256 + f0];
                s0 += b * w.x;
                s1 += b * w.y;
            }
            split_pair(Ahi, Alo, r * ASTR + f0, fmaxf(s0, 0.0f), fmaxf(s1, 0.0f));
        }

        gemm_tc(sm, smb, g_WT_hi, g_WT_lo, t, lane, wm, wn, C);

        // epilogue: feat = relu(C + W1[256+sem] + b1); macc = max(macc, feat)
        #pragma unroll
        for (int half = 0; half < 2; half++) {
            int r = wm * 16 + (lane >> 2) + half * 8;
            if (m < ncS[r]) {
                const float* wrow = W1 + ((256 + semS[r * 10 + m]) << 8);
                #pragma unroll
                for (int nt = 0; nt < 8; nt++) {
                    int col = wn * 64 + nt * 8 + (lane & 3) * 2;
                    float2 w  = *(const float2*)&wrow[col];
                    float2 bb = *(const float2*)&b1S[col];
                    float v0 = fmaxf(C[nt][half * 2 + 0] + w.x + bb.x, 0.0f);
                    float v1 = fmaxf(C[nt][half * 2 + 1] + w.y + bb.y, 0.0f);
                    float2* mp = (float2*)&maccS[r * MSTR + col];
                    float2 mo = *mp;
                    mo.x = fmaxf(mo.x, v0);
                    mo.y = fmaxf(mo.y, v1);
                    *mp = mo;
                }
            }
        }
        __syncthreads();   // macc writes done before anyone proceeds
    }

    // split macc -> A (16 pairs per thread, fixed column pair)
    #define SPLIT_MACC_TO_A()                                                  \
        do {                                                                   \
            _Pragma("unroll")                                                  \
            for (int u = 0; u < 16; u++) {                                     \
                int r = (t >> 7) + u * 4;                                      \
                float2 v = *(const float2*)&maccS[r * MSTR + f0];              \
                split_pair(Ahi, Alo, r * ASTR + f0, v.x, v.y);                 \
            }                                                                  \
        } while (0)

    // ---- parent_feat = relu(X @ W2 + b2) ----
    SPLIT_MACC_TO_A();
    gemm_tc(sm, smb, g_WT_hi + 1 * 65536, g_WT_lo + 1 * 65536, t, lane, wm, wn, C);
    #pragma unroll
    for (int half = 0; half < 2; half++) {
        int r = wm * 16 + (lane >> 2) + half * 8;
        #pragma unroll
        for (int nt = 0; nt < 8; nt++) {
            int col = wn * 64 + nt * 8 + (lane & 3) * 2;
            float2 bb = *(const float2*)&b2S[col];
            float2 v;
            v.x = fmaxf(C[nt][half * 2 + 0] + bb.x, 0.0f);
            v.y = fmaxf(C[nt][half * 2 + 1] + bb.y, 0.0f);
            *(float2*)&maccS[r * MSTR + col] = v;
        }
    }
    __syncthreads();

    // ---- enc = relu(P @ Ws1 + bs1) ----
    SPLIT_MACC_TO_A();
    gemm_tc(sm, smb, g_WT_hi + 2 * 65536, g_WT_lo + 2 * 65536, t, lane, wm, wn, C);
    #pragma unroll
    for (int half = 0; half < 2; half++) {
        int r = wm * 16 + (lane >> 2) + half * 8;
        #pragma unroll
        for (int nt = 0; nt < 8; nt++) {
            int col = wn * 64 + nt * 8 + (lane & 3) * 2;
            float2 bb = *(const float2*)&bs1S[col];
            float2 v;
            v.x = fmaxf(C[nt][half * 2 + 0] + bb.x, 0.0f);
            v.y = fmaxf(C[nt][half * 2 + 1] + bb.y, 0.0f);
            *(float2*)&maccS[r * MSTR + col] = v;
        }
    }
    __syncthreads();

    // ---- mu = enc @ Wmu + bmu (enc stays in A; macc holds mu) ----
    SPLIT_MACC_TO_A();
    gemm_tc(sm, smb, g_WT_hi + 3 * 65536, g_WT_lo + 3 * 65536, t, lane, wm, wn, C);
    #pragma unroll
    for (int half = 0; half < 2; half++) {
        int r = wm * 16 + (lane >> 2) + half * 8;
        #pragma unroll
        for (int nt = 0; nt < 8; nt++) {
            int col = wn * 64 + nt * 8 + (lane & 3) * 2;
            float2 bb = *(const float2*)&bmuS[col];
            float2 v;
            v.x = C[nt][half * 2 + 0] + bb.x;
            v.y = C[nt][half * 2 + 1] + bb.y;
            *(float2*)&maccS[r * MSTR + col] = v;   // lane-owned, reread below
        }
    }

    // ---- logvar = enc @ Wvar + bvar; sampler epilogue ----
    gemm_tc(sm, smb, g_WT_hi + 4 * 65536, g_WT_lo + 4 * 65536, t, lane, wm, wn, C);
    float* kldF = (float*)(sm + OFF_AHI);   // reuse A region: [64][264] f32
    #pragma unroll
    for (int half = 0; half < 2; half++) {
        int r = wm * 16 + (lane >> 2) + half * 8;
        int b = b0 + r;
        #pragma unroll
        for (int nt = 0; nt < 8; nt++) {
            int col = wn * 64 + nt * 8 + (lane & 3) * 2;
            float2 bb = *(const float2*)&bvarS[col];
            float2 mv = *(const float2*)&maccS[r * MSTR + col];
            float2 e  = *(const float2*)&eps[b * 256 + col];
            float lvx = C[nt][half * 2 + 0] + bb.x;
            float lvy = C[nt][half * 2 + 1] + bb.y;
            float sdx = expf(0.5f * lvx);
            float sdy = expf(0.5f * lvy);
            float2 samp, kld;
            samp.x = e.x * sdx + mv.x;
            samp.y = e.y * sdy + mv.y;
            kld.x = 1.0f + lvx - mv.x * mv.x - sdx * sdx;
            kld.y = 1.0f + lvy - mv.y * mv.y - sdy * sdy;
            *(float2*)&maccS[r * MSTR + col] = samp;
            *(float2*)&kldF[r * 264 + col] = kld;
        }
    }
    __syncthreads();

    // ---- coalesced output sweep ----
    #pragma unroll 1
    for (int u = 0; u < (PT * 256) / NT; u++) {
        int i = t + u * NT;
        int r = i >> 8, f = i & 255;
        out[(b0 + r) * 512 + f]       = maccS[r * MSTR + f];
        out[(b0 + r) * 512 + 256 + f] = kldF[r * 264 + f];
    }
}

// ================= launch =================
extern "C" void kernel_launch(void* const* d_in, const int* in_sizes, int n_in,
                              void* d_out, int out_size)
{
    const float* box   = (const float*)d_in[0];
    const float* eps   = (const float*)d_in[1];
    const float* W_box = (const float*)d_in[2];
    const float* b_box = (const float*)d_in[3];
    const float* W1    = (const float*)d_in[4];
    const float* b1    = (const float*)d_in[5];
    const float* W2    = (const float*)d_in[6];
    const float* b2    = (const float*)d_in[7];
    const float* Ws1   = (const float*)d_in[8];
    const float* bs1   = (const float*)d_in[9];
    const float* Wmu   = (const float*)d_in[10];
    const float* bmu   = (const float*)d_in[11];
    const float* Wvar  = (const float*)d_in[12];
    const float* bvar  = (const float*)d_in[13];
    const int*   sem   = (const int*)d_in[14];
    const int*   nc    = (const int*)d_in[15];
    float* out = (float*)d_out;

    prep_weights<<<(5 * 65536) / 256, 256>>>(W1, W2, Ws1, Wmu, Wvar);

    cudaFuncSetAttribute(recenc_tc_kernel,
                         cudaFuncAttributeMaxDynamicSharedMemorySize, SMEM_SZ);
    recenc_tc_kernel<<<GRID, NT, SMEM_SZ>>>(
        box, eps, W_box, b_box, W1, b1, b2, bs1, bmu, bvar, sem, nc, out);
}

// round 10
// speedup vs baseline: 1.9716x; 1.4628x over previous
#include <cuda_runtime.h>
#include <cuda_bf16.h>
#include <cstdint>

// RecursiveEncoder — mma.sync bf16 3-term split + nc-sorted child skipping.
// R9: parents bucket-sorted by n_children; block child loop runs to block max.
//     macc/mu/handoffs in registers; no smem macc buffer.

#define NT    512
#define PT    64
#define GRID  512
#define MAXC  10
#define B_N   32768

#define ASTR  264          // A row stride (bf16): conflict-free LDSM
#define WBUF  12288        // one W chunk buffer: 256 rows * 48B

// ---- smem offsets (bytes) ----
#define OFF_AHI   0          // 64*264*2 = 33792
#define OFF_ALO   33792
#define OFF_WH    67584      // 2 bufs * 12288
#define OFF_WL    92160      // 2 bufs * 12288
#define OFF_BOX   116736     // 64*10*4 = 2560
#define OFF_WBOX  119296     // 10*256*4 = 10240
#define OFF_BBOX  129536
#define OFF_B1    130560
#define OFF_B2    131584
#define OFF_BS1   132608
#define OFF_BMU   133632
#define OFF_BVAR  134656
#define OFF_SEM   135680     // 64*10*4 = 2560
#define OFF_NC    138240     // 256
#define OFF_PERM  138496     // 256
#define OFF_MAXNC 138752     // 16
#define SMEM_SZ   138768

__device__ __nv_bfloat16 g_WT_hi[5 * 65536];   // [layer][n][k]
__device__ __nv_bfloat16 g_WT_lo[5 * 65536];
__device__ int g_cnt[16];
__device__ int g_rank[B_N];
__device__ int g_perm[B_N];

static __device__ __forceinline__ uint32_t smem_u32(const void* p) {
    uint32_t a;
    asm("{ .reg .u64 t; cvta.to.shared.u64 t, %1; cvt.u32.u64 %0, t; }"
        : "=r"(a) : "l"(p));
    return a;
}
static __device__ __forceinline__ void mma16816(float d[4], const uint32_t a[4],
                                                uint32_t b0, uint32_t b1)
{
    asm volatile(
        "mma.sync.aligned.m16n8k16.row.col.f32.bf16.bf16.f32 "
        "{%0,%1,%2,%3}, {%4,%5,%6,%7}, {%8,%9}, {%0,%1,%2,%3};"
        : "+f"(d[0]), "+f"(d[1]), "+f"(d[2]), "+f"(d[3])
        : "r"(a[0]), "r"(a[1]), "r"(a[2]), "r"(a[3]), "r"(b0), "r"(b1));
}
static __device__ __forceinline__ void ldsm_x4(uint32_t r[4], uint32_t addr) {
    asm volatile("ldmatrix.sync.aligned.m8n8.x4.shared.b16 {%0,%1,%2,%3}, [%4];"
                 : "=r"(r[0]), "=r"(r[1]), "=r"(r[2]), "=r"(r[3]) : "r"(addr));
}

// ---- prep kernels ----
__global__ void prep_weights(const float* __restrict__ W1, const float* __restrict__ W2,
                             const float* __restrict__ Ws1, const float* __restrict__ Wmu,
                             const float* __restrict__ Wvar)
{
    int idx = blockIdx.x * blockDim.x + threadIdx.x;
    int l = idx >> 16;
    int e = idx & 65535;
    int n = e >> 8, k = e & 255;
    const float* src = (l == 0) ? W1 : (l == 1) ? W2 : (l == 2) ? Ws1 : (l == 3) ? Wmu : Wvar;
    float v = src[k * 256 + n];
    __nv_bfloat16 h = __float2bfloat16(v);
    g_WT_hi[idx] = h;
    g_WT_lo[idx] = __float2bfloat16(v - __bfloat162float(h));
}
__global__ void sort_zero() { if (threadIdx.x < 16) g_cnt[threadIdx.x] = 0; }
__global__ void sort_count(const int* __restrict__ nc) {
    int i = blockIdx.x * blockDim.x + threadIdx.x;
    if (i < B_N) g_rank[i] = atomicAdd(&g_cnt[nc[i] - 1], 1);
}
__global__ void sort_scatter(const int* __restrict__ nc) {
    int i = blockIdx.x * blockDim.x + threadIdx.x;
    if (i < B_N) {
        int b = nc[i] - 1;
        int base = 0;
        #pragma unroll
        for (int j = 0; j < MAXC; j++) base += (j < b) ? g_cnt[j] : 0;
        g_perm[base + g_rank[i]] = i;
    }
}

// ---- full K=256 GEMM: C[16 rows x 64 cols per warp], 3-term bf16 split ----
static __device__ __forceinline__ void gemm_tc(char* sm, uint32_t smb,
                                               const __nv_bfloat16* __restrict__ whi,
                                               const __nv_bfloat16* __restrict__ wlo,
                                               int t, int lane, int wm, int wn,
                                               float C[8][4])
{
    #pragma unroll
    for (int nt = 0; nt < 8; nt++)
        #pragma unroll
        for (int q = 0; q < 4; q++) C[nt][q] = 0.0f;

    const int arow = (lane & 7) + ((lane >> 3) & 1) * 8;
    const int akoff = (lane >> 4) * 8;
    uint32_t aHi = smb + OFF_AHI + (uint32_t)(((wm * 16 + arow) * ASTR + akoff) * 2);
    uint32_t aLo = aHi + (OFF_ALO - OFF_AHI);
    const int brow = (lane & 7) + ((lane >> 4) & 1) * 8;
    const int bkoff = ((lane >> 3) & 1) * 8;
    const uint32_t bRel = (uint32_t)(((wn * 64 + brow) * 24 + bkoff) * 2);
    const uint32_t wh0 = smb + OFF_WH, wl0 = smb + OFF_WL;

    const uint4* gh = (const uint4*)(whi + (t >> 1) * 256 + (t & 1) * 8);
    const uint4* gl = (const uint4*)(wlo + (t >> 1) * 256 + (t & 1) * 8);
    const uint32_t stoff = (uint32_t)((t >> 1) * 48 + (t & 1) * 16);

    uint4 ph = gh[0], pl = gl[0];
    *(uint4*)(sm + OFF_WH + stoff) = ph;
    *(uint4*)(sm + OFF_WL + stoff) = pl;
    __syncthreads();

    #pragma unroll 1
    for (int c = 0; c < 16; c++) {
        if (c < 15) { ph = gh[(c + 1) * 2]; pl = gl[(c + 1) * 2]; }

        const uint32_t bsel = (uint32_t)(c & 1) * WBUF;
        uint32_t ah[4], al[4];
        ldsm_x4(ah, aHi + c * 32);
        ldsm_x4(al, aLo + c * 32);
        uint32_t bh[4][4], bl[4][4];
        #pragma unroll
        for (int nt2 = 0; nt2 < 4; nt2++) {
            ldsm_x4(bh[nt2], wh0 + bsel + bRel + nt2 * 768);
            ldsm_x4(bl[nt2], wl0 + bsel + bRel + nt2 * 768);
        }
        #pragma unroll
        for (int nt2 = 0; nt2 < 4; nt2++) {
            mma16816(C[nt2 * 2],     ah, bh[nt2][0], bh[nt2][1]);
            mma16816(C[nt2 * 2 + 1], ah, bh[nt2][2], bh[nt2][3]);
        }
        #pragma unroll
        for (int nt2 = 0; nt2 < 4; nt2++) {
            mma16816(C[nt2 * 2],     al, bh[nt2][0], bh[nt2][1]);
            mma16816(C[nt2 * 2 + 1], al, bh[nt2][2], bh[nt2][3]);
        }
        #pragma unroll
        for (int nt2 = 0; nt2 < 4; nt2++) {
            mma16816(C[nt2 * 2],     ah, bl[nt2][0], bl[nt2][1]);
            mma16816(C[nt2 * 2 + 1], ah, bl[nt2][2], bl[nt2][3]);
        }

        if (c < 15) {
            const uint32_t nsel = (uint32_t)((c + 1) & 1) * WBUF;
            *(uint4*)(sm + OFF_WH + nsel + stoff) = ph;
            *(uint4*)(sm + OFF_WL + nsel + stoff) = pl;
        }
        __syncthreads();
    }
}

static __device__ __forceinline__ void split_pair(__nv_bfloat16* Ahi, __nv_bfloat16* Alo,
                                                  int idx, float s0, float s1)
{
    __nv_bfloat162 h2 = __float22bfloat162_rn(make_float2(s0, s1));
    float r0 = s0 - __bfloat162float(__low2bfloat16(h2));
    float r1 = s1 - __bfloat162float(__high2bfloat16(h2));
    __nv_bfloat162 l2 = __float22bfloat162_rn(make_float2(r0, r1));
    *(uint32_t*)&Ahi[idx] = *(uint32_t*)&h2;
    *(uint32_t*)&Alo[idx] = *(uint32_t*)&l2;
}

__global__ void __launch_bounds__(NT, 1)
recenc_tc_kernel(const float* __restrict__ box_input,
                 const float* __restrict__ eps,
                 const float* __restrict__ W_box,
                 const float* __restrict__ b_box,
                 const float* __restrict__ W1,
                 const float* __restrict__ b1,
                 const float* __restrict__ b2,
                 const float* __restrict__ bs1,
                 const float* __restrict__ bmu,
                 const float* __restrict__ bvar,
                 const int*   __restrict__ sem_ids,
                 const int*   __restrict__ n_children,
                 float*       __restrict__ out)
{
    extern __shared__ char sm[];
    const uint32_t smb = smem_u32(sm);
    __nv_bfloat16* Ahi = (__nv_bfloat16*)(sm + OFF_AHI);
    __nv_bfloat16* Alo = (__nv_bfloat16*)(sm + OFF_ALO);
    float* boxS  = (float*)(sm + OFF_BOX);
    float* wboxS = (float*)(sm + OFF_WBOX);
    float* bboxS = (float*)(sm + OFF_BBOX);
    float* b1S   = (float*)(sm + OFF_B1);
    float* b2S   = (float*)(sm + OFF_B2);
    float* bs1S  = (float*)(sm + OFF_BS1);
    float* bmuS  = (float*)(sm + OFF_BMU);
    float* bvarS = (float*)(sm + OFF_BVAR);
    int*   semS  = (int*)(sm + OFF_SEM);
    int*   ncS   = (int*)(sm + OFF_NC);
    int*   permS = (int*)(sm + OFF_PERM);
    int*   maxncS = (int*)(sm + OFF_MAXNC);

    const int t = threadIdx.x;
    const int lane = t & 31;
    const int wid = t >> 5;
    const int wm = wid >> 2;
    const int wn = wid & 3;
    const int b0 = blockIdx.x * PT;

    // ---- stage constants + permuted per-parent data ----
    for (int i = t; i < 10 * 256; i += NT) wboxS[i] = W_box[i];
    if (t < 256) {
        bboxS[t] = b_box[t];
        b1S[t]   = b1[t];
        b2S[t]   = b2[t];
        bs1S[t]  = bs1[t];
        bmuS[t]  = bmu[t];
        bvarS[t] = bvar[t];
    }
    if (t < PT) {
        int pid = g_perm[b0 + t];
        permS[t] = pid;
        ncS[t] = n_children[pid];
    }
    __syncthreads();
    for (int i = t; i < PT * 10; i += NT) semS[i] = sem_ids[permS[i / 10] * 10 + (i % 10)];
    if (t == 0) {
        int mx = 0;
        for (int i = 0; i < PT; i++) mx = max(mx, ncS[i]);
        maxncS[0] = mx;
    }
    __syncthreads();
    const int maxnc = maxncS[0];

    const int fp = t & 127;
    const int f0 = fp * 2;
    const int r_half0 = wm * 16 + (lane >> 2);     // row for half=0; +8 for half=1
    const int colq = wn * 64 + (lane & 3) * 2;     // col base; + nt*8

    float C[8][4];
    float macc[8][4];
    #pragma unroll
    for (int nt = 0; nt < 8; nt++)
        #pragma unroll
        for (int q = 0; q < 4; q++) macc[nt][q] = 0.0f;

    // ---- children loop (bounded by block max nc) ----
    for (int m = 0; m < maxnc; m++) {
        for (int i = t; i < PT * 10; i += NT)
            boxS[i] = box_input[permS[i / 10] * 100 + m * 10 + (i % 10)];
        __syncthreads();

        // leaf = relu(box @ Wbox + bbox): fixed column pair per thread
        float2 bbp = *(const float2*)&bboxS[f0];
        #pragma unroll 4
        for (int u = 0; u < 16; u++) {
            int r = (t >> 7) + u * 4;
            float s0 = bbp.x, s1 = bbp.y;
            const float* bx = &boxS[r * 10];
            #pragma unroll
            for (int q = 0; q < 10; q++) {
                float b = bx[q];
                float2 w = *(const float2*)&wboxS[q * 256 + f0];
                s0 += b * w.x;
                s1 += b * w.y;
            }
            split_pair(Ahi, Alo, r * ASTR + f0, fmaxf(s0, 0.0f), fmaxf(s1, 0.0f));
        }

        gemm_tc(sm, smb, g_WT_hi, g_WT_lo, t, lane, wm, wn, C);

        // epilogue in registers: macc = max(macc, relu(C + W1[256+sem] + b1))
        #pragma unroll
        for (int half = 0; half < 2; half++) {
            int r = r_half0 + half * 8;
            if (m < ncS[r]) {
                const float* wrow = W1 + ((256 + semS[r * 10 + m]) << 8);
                #pragma unroll
                for (int nt = 0; nt < 8; nt++) {
                    int col = colq + nt * 8;
                    float2 w  = *(const float2*)&wrow[col];
                    float2 bb = *(const float2*)&b1S[col];
                    macc[nt][half * 2 + 0] = fmaxf(macc[nt][half * 2 + 0],
                        fmaxf(C[nt][half * 2 + 0] + w.x + bb.x, 0.0f));
                    macc[nt][half * 2 + 1] = fmaxf(macc[nt][half * 2 + 1],
                        fmaxf(C[nt][half * 2 + 1] + w.y + bb.y, 0.0f));
                }
            }
        }
        // no barrier: gemm's trailing sync protects A; macc is private
    }

    // write fragment regs -> A (hi/lo), ownership (r, col) fixed
    #define FRAGS_TO_A(SRC, BIAS, RELU)                                        \
        do {                                                                   \
            _Pragma("unroll")                                                  \
            for (int half = 0; half < 2; half++) {                             \
                int r = r_half0 + half * 8;                                    \
                _Pragma("unroll")                                              \
                for (int nt = 0; nt < 8; nt++) {                               \
                    int col = colq + nt * 8;                                   \
                    float2 bb = *(const float2*)&(BIAS)[col];                  \
                    float v0 = (SRC)[nt][half * 2 + 0] + bb.x;                 \
                    float v1 = (SRC)[nt][half * 2 + 1] + bb.y;                 \
                    if (RELU) { v0 = fmaxf(v0, 0.0f); v1 = fmaxf(v1, 0.0f); }  \
                    split_pair(Ahi, Alo, r * ASTR + col, v0, v1);              \
                }                                                              \
            }                                                                  \
        } while (0)

    // ---- parent_feat = relu(X @ W2 + b2) ----
    {
        float zb[1];   // macc already has relu'd max; bias zero -> direct
        (void)zb;
    }
    #pragma unroll
    for (int half = 0; half < 2; half++) {
        int r = r_half0 + half * 8;
        #pragma unroll
        for (int nt = 0; nt < 8; nt++) {
            int col = colq + nt * 8;
            split_pair(Ahi, Alo, r * ASTR + col,
                       macc[nt][half * 2 + 0], macc[nt][half * 2 + 1]);
        }
    }
    gemm_tc(sm, smb, g_WT_hi + 1 * 65536, g_WT_lo + 1 * 65536, t, lane, wm, wn, C);
    FRAGS_TO_A(C, b2S, 1);

    // ---- enc = relu(P @ Ws1 + bs1) ----
    gemm_tc(sm, smb, g_WT_hi + 2 * 65536, g_WT_lo + 2 * 65536, t, lane, wm, wn, C);
    FRAGS_TO_A(C, bs1S, 1);

    // ---- mu = enc @ Wmu + bmu (kept in regs; A holds enc) ----
    gemm_tc(sm, smb, g_WT_hi + 3 * 65536, g_WT_lo + 3 * 65536, t, lane, wm, wn, C);
    float mu[8][4];
    #pragma unroll
    for (int half = 0; half < 2; half++)
        #pragma unroll
        for (int nt = 0; nt < 8; nt++) {
            int col = colq + nt * 8;
            float2 bb = *(const float2*)&bmuS[col];
            mu[nt][half * 2 + 0] = C[nt][half * 2 + 0] + bb.x;
            mu[nt][half * 2 + 1] = C[nt][half * 2 + 1] + bb.y;
        }

    // ---- logvar = enc @ Wvar + bvar; sampler epilogue direct to GMEM ----
    gemm_tc(sm, smb, g_WT_hi + 4 * 65536, g_WT_lo + 4 * 65536, t, lane, wm, wn, C);
    #pragma unroll
    for (int half = 0; half < 2; half++) {
        int r = r_half0 + half * 8;
        int pid = permS[r];
        #pragma unroll
        for (int nt = 0; nt < 8; nt++) {
            int col = colq + nt * 8;
            float2 bb = *(const float2*)&bvarS[col];
            float2 e  = *(const float2*)&eps[pid * 256 + col];
            float lvx = C[nt][half * 2 + 0] + bb.x;
            float lvy = C[nt][half * 2 + 1] + bb.y;
            float mvx = mu[nt][half * 2 + 0];
            float mvy = mu[nt][half * 2 + 1];
            float sdx = expf(0.5f * lvx);
            float sdy = expf(0.5f * lvy);
            float2 samp, kld;
            samp.x = e.x * sdx + mvx;
            samp.y = e.y * sdy + mvy;
            kld.x = 1.0f + lvx - mvx * mvx - sdx * sdx;
            kld.y = 1.0f + lvy - mvy * mvy - sdy * sdy;
            *(float2*)&out[pid * 512 + col]       = samp;
            *(float2*)&out[pid * 512 + 256 + col] = kld;
        }
    }
}

// ================= launch =================
extern "C" void kernel_launch(void* const* d_in, const int* in_sizes, int n_in,
                              void* d_out, int out_size)
{
    const float* box   = (const float*)d_in[0];
    const float* eps   = (const float*)d_in[1];
    const float* W_box = (const float*)d_in[2];
    const float* b_box = (const float*)d_in[3];
    const float* W1    = (const float*)d_in[4];
    const float* b1    = (const float*)d_in[5];
    const float* W2    = (const float*)d_in[6];
    const float* b2    = (const float*)d_in[7];
    const float* Ws1   = (const float*)d_in[8];
    const float* bs1   = (const float*)d_in[9];
    const float* Wmu   = (const float*)d_in[10];
    const float* bmu   = (const float*)d_in[11];
    const float* Wvar  = (const float*)d_in[12];
    const float* bvar  = (const float*)d_in[13];
    const int*   sem   = (const int*)d_in[14];
    const int*   nc    = (const int*)d_in[15];
    float* out = (float*)d_out;

    prep_weights<<<(5 * 65536) / 256, 256>>>(W1, W2, Ws1, Wmu, Wvar);
    sort_zero<<<1, 32>>>();
    sort_count<<<B_N / 256, 256>>>(nc);
    sort_scatter<<<B_N / 256, 256>>>(nc);

    cudaFuncSetAttribute(recenc_tc_kernel,
                         cudaFuncAttributeMaxDynamicSharedMemorySize, SMEM_SZ);
    recenc_tc_kernel<<<GRID, NT, SMEM_SZ>>>(
        box, eps, W_box, b_box, W1, b1, b2, bs1, bmu, bvar, sem, nc, out);
}